// round 17
// baseline (speedup 1.0000x reference)
#include <cuda_runtime.h>
#include <cuda_fp16.h>
#include <math.h>

// Problem constants
#define BB 32
#define CC 16
#define LL 4096
#define SS 64
#define KK 64
#define WW 4033            // LL - SS + 1

#define W_TILE 128
#define NT 256             // 8 warps: wid&3 -> m32 tile, wid>>2 -> k-half (n32)
#define XS_STRIDE 200      // f32 staging elems per c (need 192)
#define PLEN_B 400         // bytes per parity copy (addressing stride; 96 words built)
#define PWORDS 96          // words built per copy (A reads word index <= 94)

// ---------------- dynamic smem layout (bytes) ----------------
#define OFF_XHL 0                              // [c][p] fp16 parity copies: 16*2*400 = 12800
#define OFF_B   12800                          // 8 x 8192 = 65536 (two 4-buffer sets)
#define OFF_INV 78336                          // CC*W_TILE floats = 8192
#define OFF_XS  86528                          // CC*XS_STRIDE f32 = 12800
#define SMEM_BYTES 99328

typedef unsigned int u32;

// Global scratch
__device__ __align__(16) unsigned char g_shb[CC * 8192];  // per-c swizzled fp16 B image

// ---------------- helpers ----------------
__device__ __forceinline__ u32 smem_u32(const void* p) {
    u32 a;
    asm("{ .reg .u64 t; cvta.to.shared.u64 t, %1; cvt.u32.u64 %0, t; }" : "=r"(a) : "l"(p));
    return a;
}
__device__ __forceinline__ u32 swz128(u32 off) { return off ^ ((off >> 3) & 0x70); }

__device__ __forceinline__ void cp16(u32 dst, const void* src) {
    asm volatile("cp.async.cg.shared.global [%0], [%1], 16;"
                 :: "r"(dst), "l"(src) : "memory");
}
#define CP_COMMIT() asm volatile("cp.async.commit_group;" ::: "memory")
#define CP_WAIT0()  asm volatile("cp.async.wait_group 0;" ::: "memory")

__device__ __forceinline__ void ldsm4(u32& r0, u32& r1, u32& r2, u32& r3, u32 addr) {
    asm volatile("ldmatrix.sync.aligned.m8n8.x4.shared.b16 {%0,%1,%2,%3}, [%4];"
                 : "=r"(r0), "=r"(r1), "=r"(r2), "=r"(r3) : "r"(addr));
}
__device__ __forceinline__ u32 lds32(u32 addr) {
    u32 v;
    asm volatile("ld.shared.b32 %0, [%1];" : "=r"(v) : "r"(addr));
    return v;
}
__device__ __forceinline__ void mma_f16(float* d, u32 a0, u32 a1, u32 a2, u32 a3,
                                        u32 b0, u32 b1) {
    asm volatile(
        "mma.sync.aligned.m16n8k16.row.col.f32.f16.f16.f32 "
        "{%0,%1,%2,%3}, {%4,%5,%6,%7}, {%8,%9}, {%0,%1,%2,%3};"
        : "+f"(d[0]), "+f"(d[1]), "+f"(d[2]), "+f"(d[3])
        : "r"(a0), "r"(a1), "r"(a2), "r"(a3), "r"(b0), "r"(b1));
}

// ---------------------------------------------------------------------------
// Prep: normalize shapelets, fp16, write swizzled B image per c.
// Blocks 0..63 additionally zero the 2048-float output.
// ---------------------------------------------------------------------------
__global__ void norm_shapelets_kernel(const float* __restrict__ sh,
                                      float* __restrict__ out) {
    int row  = blockIdx.x;          // c*KK + k
    int c    = row / KK;
    int k    = row - c * KK;
    int lane = threadIdx.x;
    if (row < 64) out[row * 32 + lane] = 0.0f;   // zero out (64*32 = 2048)
    const float* p = sh + (size_t)row * SS;
    float v0 = p[lane];
    float v1 = p[lane + 32];
    float ss = v0 * v0 + v1 * v1;
    #pragma unroll
    for (int o = 16; o > 0; o >>= 1) ss += __shfl_xor_sync(0xffffffffu, ss, o);
    float inv = 1.0f / fmaxf(sqrtf(ss), 1e-8f);

    unsigned char* img = g_shb + c * 8192;
    #pragma unroll
    for (int h = 0; h < 2; ++h) {
        int s = lane + 32 * h;
        float vn = (h ? v1 : v0) * inv;
        __half hv = __float2half_rn(vn);
        u32 sw = swz128((u32)(k * 128 + s * 2));
        *(unsigned short*)(img + sw) = *(unsigned short*)&hv;
    }
}

__device__ __forceinline__ float inv_norm(float ss) {
    return (ss > 1e-16f) ? rsqrtf(ss) : 1e8f;
}

// ---------------------------------------------------------------------------
// Main: per (b, 128-w tile). Single-term fp16 MMA; Hankel A = 11 broadcast
// LDS.32 per warp per c. Channels processed in GROUPS OF 4: cp.async stages
// the next 4-channel B set while the current set computes -> 4 barriers,
// 128 independent MMAs per span. inv-norms inline in prologue; fp32 fold.
// ---------------------------------------------------------------------------
__global__ void __launch_bounds__(NT, 2)
max_cossim_kernel(const float* __restrict__ x, float* __restrict__ out) {
    extern __shared__ unsigned char smem[];
    const u32 sbase = smem_u32(smem);
    const int b  = blockIdx.y;
    const int w0 = blockIdx.x * W_TILE;
    const int t  = threadIdx.x;
    const int wid = t >> 5, lane = t & 31;

    float* xs   = (float*)(smem + OFF_XS);
    float* invs = (float*)(smem + OFF_INV);

    // B staging: 8192 B per channel, 32 B per thread via 2 cp.async.
    auto stageB = [&](int cc, int bufidx) {
        const unsigned char* src = g_shb + (size_t)cc * 8192;
        u32 dst = sbase + OFF_B + (u32)bufidx * 8192;
        cp16(dst + t * 16,        src + t * 16);
        cp16(dst + t * 16 + 4096, src + t * 16 + 4096);
    };

    // ---- Prologue 1: stage raw x tile (f32, zero-padded) ----
    const float* xb = x + (size_t)b * CC * LL;
    for (int idx = t; idx < CC * XS_STRIDE; idx += NT) {
        int c = idx / XS_STRIDE, j = idx - c * XS_STRIDE;
        int gw = w0 + j;
        xs[idx] = (gw < LL && j < 192) ? xb[(size_t)c * LL + gw] : 0.0f;
    }
    // Kick off B staging for channels 0..3 (overlaps with prologue 2).
    stageB(0, 0); stageB(1, 1); stageB(2, 2); stageB(3, 3);
    CP_COMMIT();
    __syncthreads();

    // ---- Prologue 2a: inline window inv-norms (8 windows per thread) ----
    {
        int c  = t >> 4;
        int wb = (t & 15) * 8;
        const float* xr = xs + c * XS_STRIDE + wb;
        float* dst = invs + c * W_TILE + wb;
        float ss = 0.0f;
        #pragma unroll
        for (int s = 0; s < SS; ++s) { float v = xr[s]; ss = fmaf(v, v, ss); }
        dst[0] = (w0 + wb < WW) ? inv_norm(ss) : 0.0f;
        #pragma unroll
        for (int j = 1; j < 8; ++j) {
            float a = xr[j + SS - 1], s0 = xr[j - 1];
            ss = fmaf(a, a, ss);
            ss = fmaf(-s0, s0, ss);
            dst[j] = (w0 + wb + j < WW) ? inv_norm(ss) : 0.0f;
        }
    }
    // ---- Prologue 2b: fp16 parity copies for all channels ----
    // word layout: [c*2+p][w], w < PWORDS=96 (A reads word index <= 94).
    for (int idx = t; idx < 16 * 2 * PWORDS; idx += NT) {
        int w = idx % PWORDS;
        int r = idx / PWORDS;         // c*2+p
        int p = r & 1, c = r >> 1;
        int e = 2 * w + p;
        __half2 h2 = __floats2half2_rn(xs[c * XS_STRIDE + e], xs[c * XS_STRIDE + e + 1]);
        *(u32*)(smem + OFF_XHL + r * PLEN_B + w * 4) = *(u32*)&h2;
    }
    CP_WAIT0();
    __syncthreads();

    // ---- Fragment addressing ----
    const int g  = lane >> 2, q = lane & 3;
    const int e0 = (wid & 3) * 32 + g + 2 * q;
    const int pA = g & 1;
    const int rx    = lane & 7;
    const int bn8   = (lane >> 4) & 1;
    const int bhalf = (lane >> 3) & 1;
    const int pbase = (wid >> 2) * 2;       // k-half ntile-pair base

    float acc[32];                          // [m(2)][nt(4)][4]
    #pragma unroll
    for (int i = 0; i < 32; ++i) acc[i] = 0.0f;

    // Per-channel compute: A t-loads (Hankel collapse: a1==a2, a3(j)==a0(j+1)),
    // 32 MMAs, fp32 fold of inv.
    auto compute_c = [&](int c, u32 Bb) {
        const float* ivp = invs + c * W_TILE + (wid & 3) * 32;
        const float iv0 = ivp[g], iv1 = ivp[g + 8], iv2 = ivp[g + 16], iv3 = ivp[g + 24];

        u32 th[11];
        {
            u32 aH = sbase + OFF_XHL + (u32)(c * 2 + pA) * PLEN_B + (u32)(e0 - pA) * 2;
            #pragma unroll
            for (int i = 0; i < 11; ++i) th[i] = lds32(aH + 16 * i);
        }

        float dot[32];
        #pragma unroll
        for (int i = 0; i < 32; ++i) dot[i] = 0.0f;

        #pragma unroll
        for (int j = 0; j < 4; ++j) {
            u32 bch = (u32)(((2 * j + bhalf) ^ rx) * 16);
            #pragma unroll
            for (int p = 0; p < 2; ++p) {
                u32 boff = (u32)(((pbase + p) * 16 + bn8 * 8 + rx) * 128) + bch;
                u32 b0, b1, b2, b3;
                ldsm4(b0, b1, b2, b3, Bb + boff);
                float* d00 = dot + (0 * 4 + 2 * p) * 4;
                float* d01 = dot + (0 * 4 + 2 * p + 1) * 4;
                float* d10 = dot + (1 * 4 + 2 * p) * 4;
                float* d11 = dot + (1 * 4 + 2 * p + 1) * 4;
                mma_f16(d00, th[2*j], th[2*j+1], th[2*j+1], th[2*j+2], b0, b1);
                mma_f16(d01, th[2*j], th[2*j+1], th[2*j+1], th[2*j+2], b2, b3);
                mma_f16(d10, th[2*j+2], th[2*j+3], th[2*j+3], th[2*j+4], b0, b1);
                mma_f16(d11, th[2*j+2], th[2*j+3], th[2*j+3], th[2*j+4], b2, b3);
            }
        }

        #pragma unroll
        for (int nt = 0; nt < 4; ++nt) {
            acc[nt * 4 + 0]      = fmaf(iv0, dot[nt * 4 + 0],      acc[nt * 4 + 0]);
            acc[nt * 4 + 1]      = fmaf(iv0, dot[nt * 4 + 1],      acc[nt * 4 + 1]);
            acc[nt * 4 + 2]      = fmaf(iv1, dot[nt * 4 + 2],      acc[nt * 4 + 2]);
            acc[nt * 4 + 3]      = fmaf(iv1, dot[nt * 4 + 3],      acc[nt * 4 + 3]);
            acc[16 + nt * 4 + 0] = fmaf(iv2, dot[16 + nt * 4 + 0], acc[16 + nt * 4 + 0]);
            acc[16 + nt * 4 + 1] = fmaf(iv2, dot[16 + nt * 4 + 1], acc[16 + nt * 4 + 1]);
            acc[16 + nt * 4 + 2] = fmaf(iv3, dot[16 + nt * 4 + 2], acc[16 + nt * 4 + 2]);
            acc[16 + nt * 4 + 3] = fmaf(iv3, dot[16 + nt * 4 + 3], acc[16 + nt * 4 + 3]);
        }
    };

    // ---- Mainloop: 4 channels per barrier; cp.async next set meanwhile ----
    #pragma unroll 1
    for (int cs = 0; cs < CC; cs += 4) {
        const int s = (cs >> 2) & 1;                 // current buffer set
        if (cs + 4 < CC) {
            stageB(cs + 4, (s ^ 1) * 4 + 0);
            stageB(cs + 5, (s ^ 1) * 4 + 1);
            stageB(cs + 6, (s ^ 1) * 4 + 2);
            stageB(cs + 7, (s ^ 1) * 4 + 3);
            CP_COMMIT();
        }
        compute_c(cs,     sbase + OFF_B + (u32)(s * 4 + 0) * 8192);
        compute_c(cs + 1, sbase + OFF_B + (u32)(s * 4 + 1) * 8192);
        compute_c(cs + 2, sbase + OFF_B + (u32)(s * 4 + 2) * 8192);
        compute_c(cs + 3, sbase + OFF_B + (u32)(s * 4 + 3) * 8192);
        if (cs + 4 < CC) CP_WAIT0();
        __syncthreads();   // next set landed for all warps; current reads done
    }

    // ---- epilogue: max over w per k ----
    float cm[8];
    #pragma unroll
    for (int nt = 0; nt < 4; ++nt) {
        cm[2 * nt] = fmaxf(fmaxf(acc[nt * 4 + 0], acc[nt * 4 + 2]),
                           fmaxf(acc[16 + nt * 4 + 0], acc[16 + nt * 4 + 2]));
        cm[2 * nt + 1] = fmaxf(fmaxf(acc[nt * 4 + 1], acc[nt * 4 + 3]),
                               fmaxf(acc[16 + nt * 4 + 1], acc[16 + nt * 4 + 3]));
    }
    #pragma unroll
    for (int m = 4; m < 32; m <<= 1) {
        #pragma unroll
        for (int i = 0; i < 8; ++i)
            cm[i] = fmaxf(cm[i], __shfl_xor_sync(0xffffffffu, cm[i], m));
    }
    float* red = (float*)(smem + OFF_XHL);  // [8 warps][64 cols]
    if (lane < 4) {
        int kb = (wid >> 2) * 32;
        #pragma unroll
        for (int nt = 0; nt < 4; ++nt) {
            red[wid * 64 + kb + nt * 8 + lane * 2 + 0] = cm[2 * nt];
            red[wid * 64 + kb + nt * 8 + lane * 2 + 1] = cm[2 * nt + 1];
        }
    }
    __syncthreads();
    if (t < KK) {
        int g0 = (t >> 5) * 4;              // warps holding this k-half
        float m = 0.0f;                     // relu floor
        #pragma unroll
        for (int i = 0; i < 4; ++i) m = fmaxf(m, red[(g0 + i) * 64 + t]);
        m *= (1.0f / (float)CC);
        // m >= 0: float bits monotone, int atomicMax exact (out zero-initialized).
        atomicMax((int*)&out[b * KK + t], __float_as_int(m));
    }
}

// ---------------------------------------------------------------------------
// Launch
// ---------------------------------------------------------------------------
extern "C" void kernel_launch(void* const* d_in, const int* in_sizes, int n_in,
                              void* d_out, int out_size) {
    const float* x  = (const float*)d_in[0];   // (32,16,4096) f32
    const float* sh = (const float*)d_in[1];   // (16,64,64)  f32
    float* out = (float*)d_out;                // (32,1,64)   f32

    cudaFuncSetAttribute(max_cossim_kernel,
                         cudaFuncAttributeMaxDynamicSharedMemorySize, SMEM_BYTES);

    norm_shapelets_kernel<<<CC * KK, 32>>>(sh, out);

    dim3 grid((WW + W_TILE - 1) / W_TILE, BB);   // (32, 32)
    max_cossim_kernel<<<grid, NT, SMEM_BYTES>>>(x, out);
}